// round 1
// baseline (speedup 1.0000x reference)
#include <cuda_runtime.h>
#include <cuda_bf16.h>

#define BATCH   4096
#define DIM     16
#define NMF     4
#define NRULES  1024
#define NCLS    10
#define IEXT    17          // DIM + 1
#define NCOLS   170         // IEXT * NCLS
#define NPAD    192         // padded GEMM N
#define KSPLIT  8
#define KPER    (NRULES / KSPLIT)   // 128

// ---- static device scratch (no allocation allowed in kernel_launch) ----
__device__ float g_OT[64 * NRULES];            // one-hot, transposed [j=d*4+m][r]  (256 KB)
__device__ float g_Cpad[NRULES * NPAD];        // consequents padded  (768 KB)
__device__ float g_Z[BATCH * 64];              // membership logits   (1 MB)
__device__ float g_inv[BATCH];                 // 1/(rowsum+1e-9)
__device__ float g_Tp[KSPLIT * BATCH * NPAD];  // split-K partials    (25.2 MB)

// =====================================================================
// Prep: one-hot matrix, padded consequents, Z table, x_ext output.
// Total elements = 65536 + 196608 + 262144 + 69632 = 593920 = 2320*256
// =====================================================================
__global__ void k_prep(const float* __restrict__ x,
                       const float* __restrict__ centers,
                       const float* __restrict__ widths,
                       const float* __restrict__ conseq,
                       const int*   __restrict__ ridx,
                       float* __restrict__ out_xext)
{
    int i = blockIdx.x * 256 + threadIdx.x;
    if (i < 65536) {
        // OT[j][r], j = d*4 + m
        int j = i >> 10, r = i & 1023;
        int d = j >> 2,  m = j & 3;
        g_OT[j * NRULES + r] = (ridx[d * NRULES + r] == m) ? 1.0f : 0.0f;
    } else if (i < 65536 + 196608) {
        int e = i - 65536;
        int r = e / NPAD, col = e % NPAD;
        g_Cpad[e] = (col < NCOLS) ? conseq[r * NCOLS + col] : 0.0f;
    } else if (i < 65536 + 196608 + 262144) {
        int e = i - (65536 + 196608);      // e = b*64 + j
        int b = e >> 6, j = e & 63;
        int d = j >> 2;
        float xv = x[b * DIM + d];
        float c  = centers[j];             // centers[d][m] row-major == centers[j]
        float w  = widths[j];
        float df = xv - c;
        g_Z[e] = -(df * df) / (2.0f * w * w) + 1e-9f;
    } else {
        int e = i - (65536 + 196608 + 262144);
        if (e < BATCH * IEXT) {
            int b = e / IEXT, ii = e % IEXT;
            out_xext[e] = (ii < DIM) ? x[b * DIM + ii] : 1.0f;
        }
    }
}

// =====================================================================
// Firing: logits = Z[32x64] @ OT[64x1024] per block, exp, rowsum.
// 128 blocks x 256 threads. Writes UNNORMALIZED firing into out_norm,
// writes 1/(rowsum+1e-9) into g_inv. Dynamic smem: Zs(8KB)+Os(64KB)+rs.
// =====================================================================
__global__ __launch_bounds__(256, 1) void k_fire(float* __restrict__ out_norm)
{
    extern __shared__ float smem[];
    float* Zs = smem;                  // [32][64]
    float* Os = smem + 32 * 64;        // [64][256] (per column-chunk)
    float* rs = Os + 64 * 256;         // [32]

    const int t  = threadIdx.x;
    const int b0 = blockIdx.x * 32;
    const int tx = t & 31;             // column group: cols tx*8..tx*8+7
    const int ty = t >> 5;             // row group:    rows ty*4..ty*4+3

    // load Z tile (2048 floats)
    {
        float4* Zs4 = (float4*)Zs;
        const float4* Zg4 = (const float4*)(g_Z + b0 * 64);
        for (int i = t; i < 512; i += 256) Zs4[i] = Zg4[i];
    }

    float rsum[4] = {0.f, 0.f, 0.f, 0.f};
    float4* Os4 = (float4*)Os;

    for (int ch = 0; ch < 4; ch++) {
        __syncthreads();
        // load OT column chunk: rows k=0..63, cols ch*256..ch*256+255
        for (int f = t; f < 4096; f += 256) {
            int k = f >> 6, c4 = f & 63;
            Os4[f] = ((const float4*)g_OT)[k * 256 + ch * 64 + c4];
        }
        __syncthreads();

        float acc[4][8];
#pragma unroll
        for (int q = 0; q < 4; q++)
#pragma unroll
            for (int j = 0; j < 8; j++) acc[q][j] = 0.f;

#pragma unroll 16
        for (int k = 0; k < 64; k++) {
            float4 bA = Os4[k * 64 + tx * 2];
            float4 bB = Os4[k * 64 + tx * 2 + 1];
#pragma unroll
            for (int q = 0; q < 4; q++) {
                float a = Zs[(ty * 4 + q) * 64 + k];
                acc[q][0] += a * bA.x; acc[q][1] += a * bA.y;
                acc[q][2] += a * bA.z; acc[q][3] += a * bA.w;
                acc[q][4] += a * bB.x; acc[q][5] += a * bB.y;
                acc[q][6] += a * bB.z; acc[q][7] += a * bB.w;
            }
        }

#pragma unroll
        for (int q = 0; q < 4; q++) {
            float4 e0, e1;
            e0.x = __expf(acc[q][0]); e0.y = __expf(acc[q][1]);
            e0.z = __expf(acc[q][2]); e0.w = __expf(acc[q][3]);
            e1.x = __expf(acc[q][4]); e1.y = __expf(acc[q][5]);
            e1.z = __expf(acc[q][6]); e1.w = __expf(acc[q][7]);
            rsum[q] += (e0.x + e0.y) + (e0.z + e0.w) + (e1.x + e1.y) + (e1.z + e1.w);
            int row = b0 + ty * 4 + q;
            float4* op = (float4*)(out_norm + row * NRULES + ch * 256 + tx * 8);
            op[0] = e0; op[1] = e1;
        }
    }

    // warp-reduce rsum (all lanes of a warp share the same 4 rows)
#pragma unroll
    for (int off = 16; off > 0; off >>= 1)
#pragma unroll
        for (int q = 0; q < 4; q++)
            rsum[q] += __shfl_xor_sync(0xffffffffu, rsum[q], off);
    if (tx == 0)
#pragma unroll
        for (int q = 0; q < 4; q++) rs[ty * 4 + q] = rsum[q];
    __syncthreads();
    if (t < 32) g_inv[b0 + t] = 1.0f / (rs[t] + 1e-9f);
}

// =====================================================================
// Normalize firing -> norm_fs (in place in d_out). 1,048,576 float4s.
// =====================================================================
__global__ void k_norm(float* __restrict__ out_norm)
{
    int i = blockIdx.x * 256 + threadIdx.x;   // float4 index
    float4* p = (float4*)out_norm;
    float4 v = p[i];
    float inv = g_inv[i >> 8];                // 256 float4 per batch row
    v.x *= inv; v.y *= inv; v.z *= inv; v.w *= inv;
    p[i] = v;
}

// =====================================================================
// GEMM: T[b, j] = sum_k norm[b,k] * Cpad[k, j]   (M=4096, N=192, K=1024)
// block = 128 rows x 192 cols, split-K x8 -> 256 blocks.
// thread tile 8 rows x 12 cols (96 acc). Deterministic partials in g_Tp.
// =====================================================================
__global__ __launch_bounds__(256, 1) void k_gemm(const float* __restrict__ norm)
{
    __shared__ float As[32 * 128];    // [k][row]  16 KB
    __shared__ float Bs[32 * NPAD];   // [k][col]  24 KB

    const int t  = threadIdx.x;
    const int rg = t >> 4;            // 0..15 -> rows rg*8..rg*8+7
    const int cg = t & 15;            // 0..15 -> cols cg*12..cg*12+11
    const int b0 = blockIdx.x * 128;
    const int k0 = blockIdx.y * KPER;

    float acc[8][12];
#pragma unroll
    for (int q = 0; q < 8; q++)
#pragma unroll
        for (int j = 0; j < 12; j++) acc[q][j] = 0.f;

    for (int kt = 0; kt < KPER; kt += 32) {
        __syncthreads();
        // As: 128 rows x 32 k  (1024 float4 loads, transpose to [k][row])
        for (int f = t; f < 1024; f += 256) {
            int row = f >> 3, kq = f & 7;
            float4 v = *(const float4*)(norm + (b0 + row) * NRULES + k0 + kt + kq * 4);
            As[(kq * 4 + 0) * 128 + row] = v.x;
            As[(kq * 4 + 1) * 128 + row] = v.y;
            As[(kq * 4 + 2) * 128 + row] = v.z;
            As[(kq * 4 + 3) * 128 + row] = v.w;
        }
        // Bs: 32 k x 192 cols (1536 float4)
        for (int f = t; f < 1536; f += 256) {
            int k = f / 48, c4 = f % 48;
            ((float4*)Bs)[k * 48 + c4] =
                ((const float4*)g_Cpad)[(k0 + kt + k) * 48 + c4];
        }
        __syncthreads();

#pragma unroll 4
        for (int k = 0; k < 32; k++) {
            float a[8];
#pragma unroll
            for (int q = 0; q < 8; q++) a[q] = As[k * 128 + rg * 8 + q];
            const float4* br = (const float4*)(Bs + k * NPAD + cg * 12);
            float4 bv0 = br[0], bv1 = br[1], bv2 = br[2];
#pragma unroll
            for (int q = 0; q < 8; q++) {
                acc[q][0]  += a[q] * bv0.x; acc[q][1]  += a[q] * bv0.y;
                acc[q][2]  += a[q] * bv0.z; acc[q][3]  += a[q] * bv0.w;
                acc[q][4]  += a[q] * bv1.x; acc[q][5]  += a[q] * bv1.y;
                acc[q][6]  += a[q] * bv1.z; acc[q][7]  += a[q] * bv1.w;
                acc[q][8]  += a[q] * bv2.x; acc[q][9]  += a[q] * bv2.y;
                acc[q][10] += a[q] * bv2.z; acc[q][11] += a[q] * bv2.w;
            }
        }
    }

    float* Tp = g_Tp + (size_t)blockIdx.y * (BATCH * NPAD);
#pragma unroll
    for (int q = 0; q < 8; q++) {
        int row = b0 + rg * 8 + q;
        float* o = Tp + row * NPAD + cg * 12;
        ((float4*)o)[0] = make_float4(acc[q][0], acc[q][1], acc[q][2],  acc[q][3]);
        ((float4*)o)[1] = make_float4(acc[q][4], acc[q][5], acc[q][6],  acc[q][7]);
        ((float4*)o)[2] = make_float4(acc[q][8], acc[q][9], acc[q][10], acc[q][11]);
    }
}

// =====================================================================
// y_hat[b,c] = sum_i xext[b,i] * sum_s Tp[s][b, i*10+c]
// 40960 outputs -> 160 blocks x 256 threads
// =====================================================================
__global__ void k_yhat(const float* __restrict__ xext, float* __restrict__ out_y)
{
    int i = blockIdx.x * 256 + threadIdx.x;
    if (i >= BATCH * NCLS) return;
    int b = i / NCLS, c = i % NCLS;
    const float* tb = g_Tp + b * NPAD;
    const float* xe = xext + b * IEXT;
    float y = 0.f;
#pragma unroll
    for (int ii = 0; ii < IEXT; ii++) {
        float tsum = 0.f;
#pragma unroll
        for (int s = 0; s < KSPLIT; s++)
            tsum += tb[(size_t)s * (BATCH * NPAD) + ii * NCLS + c];
        y += xe[ii] * tsum;
    }
    out_y[i] = y;
}

// =====================================================================
extern "C" void kernel_launch(void* const* d_in, const int* in_sizes, int n_in,
                              void* d_out, int out_size)
{
    const float* x       = (const float*)d_in[0];
    const float* centers = (const float*)d_in[1];
    const float* widths  = (const float*)d_in[2];
    const float* conseq  = (const float*)d_in[3];
    const int*   ridx    = (const int*)  d_in[4];

    float* out       = (float*)d_out;
    float* out_y     = out;                              // [4096,10]
    float* out_norm  = out + BATCH * NCLS;               // [4096,1024]
    float* out_xext  = out + BATCH * NCLS + BATCH * NRULES; // [4096,17]

    static bool attr_set = false;
    const int SMEM_FIRE = (32 * 64 + 64 * 256 + 32) * (int)sizeof(float); // ~73.9 KB
    if (!attr_set) {
        cudaFuncSetAttribute(k_fire, cudaFuncAttributeMaxDynamicSharedMemorySize, SMEM_FIRE);
        attr_set = true;
    }

    k_prep<<<2320, 256>>>(x, centers, widths, conseq, ridx, out_xext);
    k_fire<<<128, 256, SMEM_FIRE>>>(out_norm);
    k_norm<<<4096, 256>>>(out_norm);
    dim3 gg(32, KSPLIT);
    k_gemm<<<gg, 256>>>(out_norm);
    k_yhat<<<160, 256>>>(out_xext, out_y);
}

// round 4
// speedup vs baseline: 1.7137x; 1.7137x over previous
#include <cuda_runtime.h>
#include <cuda_bf16.h>
#include <cstdint>

#define BATCH   4096
#define DIM     16
#define NRULES  1024
#define NCLS    10
#define IEXT    17
#define NCOLS   170
#define NPAD    192
#define KSPLIT  4
#define KTOT    3072                 // 3 passes x 1024 (ah*bh, ah*bl, al*bh)
#define KLOC    (KTOT / KSPLIT)      // 768
#define NCH     (KLOC / 64)          // 12 chunks of K=64 per CTA

// single TU-wide dynamic smem symbol
extern __shared__ char dyn_smem[];

// ---------------- static device scratch ----------------
__device__ float         g_OT[64 * NRULES];
__device__ float         g_Z[BATCH * 64];
__device__ float         g_inv[BATCH];
__device__ __nv_bfloat16 g_Ah[BATCH * NRULES];
__device__ __nv_bfloat16 g_Al[BATCH * NRULES];
__device__ __nv_bfloat16 g_Bh[NPAD * NRULES];
__device__ __nv_bfloat16 g_Bl[NPAD * NRULES];
__device__ float         g_Tp[KSPLIT * BATCH * NPAD];   // 12.6 MB partials

// ---------------- helpers ----------------
__device__ __forceinline__ uint32_t smem_u32(const void* p) {
    uint32_t a;
    asm("{ .reg .u64 t; cvta.to.shared.u64 t, %1; cvt.u32.u64 %0, t; }" : "=r"(a) : "l"(p));
    return a;
}
#define SWZ128(o) ((o) ^ (((o) >> 3) & 0x70))

#define CP_ASYNC16(dst, src) \
    asm volatile("cp.async.cg.shared.global [%0], [%1], 16;" :: "r"(dst), "l"(src))
#define CP_COMMIT() asm volatile("cp.async.commit_group;" ::: "memory")
#define CP_WAIT1()  asm volatile("cp.async.wait_group 1;" ::: "memory")
#define CP_WAIT0()  asm volatile("cp.async.wait_group 0;" ::: "memory")

#define LDSM_X4(r0, r1, r2, r3, addr)                                        \
    asm volatile("ldmatrix.sync.aligned.m8n8.x4.shared.b16 {%0,%1,%2,%3}, [%4];" \
        : "=r"(r0), "=r"(r1), "=r"(r2), "=r"(r3) : "r"(addr))

__device__ __forceinline__ void mma16816(float* c, const uint32_t* a, const uint32_t* b) {
    asm volatile(
        "mma.sync.aligned.m16n8k16.row.col.f32.bf16.bf16.f32 "
        "{%0,%1,%2,%3}, {%4,%5,%6,%7}, {%8,%9}, {%0,%1,%2,%3};"
        : "+f"(c[0]), "+f"(c[1]), "+f"(c[2]), "+f"(c[3])
        : "r"(a[0]), "r"(a[1]), "r"(a[2]), "r"(a[3]), "r"(b[0]), "r"(b[1]));
}

// =====================================================================
// k_prep: one-hot OT, Bh/Bl (bf16 hi/lo of consequents, [n][k] layout),
//         Z logits, x_ext. 65536+196608+262144+69632 = 593920 = 2320*256
// =====================================================================
__global__ void k_prep(const float* __restrict__ x,
                       const float* __restrict__ centers,
                       const float* __restrict__ widths,
                       const float* __restrict__ conseq,
                       const int*   __restrict__ ridx,
                       float* __restrict__ out_xext)
{
    int i = blockIdx.x * 256 + threadIdx.x;
    if (i < 65536) {
        int j = i >> 10, r = i & 1023;
        int d = j >> 2,  m = j & 3;
        g_OT[j * NRULES + r] = (ridx[d * NRULES + r] == m) ? 1.0f : 0.0f;
    } else if (i < 65536 + 196608) {
        int e = i - 65536;
        int n = e >> 10, k = e & 1023;
        float v = (n < NCOLS) ? conseq[k * NCOLS + n] : 0.0f;
        __nv_bfloat16 h = __float2bfloat16_rn(v);
        g_Bh[e] = h;
        g_Bl[e] = __float2bfloat16_rn(v - __bfloat162float(h));
    } else if (i < 65536 + 196608 + 262144) {
        int e = i - (65536 + 196608);
        int b = e >> 6, j = e & 63;
        int d = j >> 2;
        float xv = x[b * DIM + d];
        float c  = centers[j];
        float w  = widths[j];
        float df = xv - c;
        g_Z[e] = -(df * df) / (2.0f * w * w) + 1e-9f;
    } else {
        int e = i - (65536 + 196608 + 262144);
        if (e < BATCH * IEXT) {
            int b = e / IEXT, ii = e % IEXT;
            out_xext[e] = (ii < DIM) ? x[b * DIM + ii] : 1.0f;
        }
    }
}

// =====================================================================
// k_fire: logits = Z[32x64] @ OT[64x1024] per block, exp, rowsum.
// =====================================================================
__global__ __launch_bounds__(256, 1) void k_fire(float* __restrict__ out_norm)
{
    float* smem = (float*)dyn_smem;
    float* Zs = smem;
    float* Os = smem + 32 * 64;
    float* rs = Os + 64 * 256;

    const int t  = threadIdx.x;
    const int b0 = blockIdx.x * 32;
    const int tx = t & 31;
    const int ty = t >> 5;

    {
        float4* Zs4 = (float4*)Zs;
        const float4* Zg4 = (const float4*)(g_Z + b0 * 64);
        for (int i = t; i < 512; i += 256) Zs4[i] = Zg4[i];
    }

    float rsum[4] = {0.f, 0.f, 0.f, 0.f};
    float4* Os4 = (float4*)Os;

    for (int ch = 0; ch < 4; ch++) {
        __syncthreads();
        for (int f = t; f < 4096; f += 256) {
            int k = f >> 6, c4 = f & 63;
            Os4[f] = ((const float4*)g_OT)[k * 256 + ch * 64 + c4];
        }
        __syncthreads();

        float acc[4][8];
#pragma unroll
        for (int q = 0; q < 4; q++)
#pragma unroll
            for (int j = 0; j < 8; j++) acc[q][j] = 0.f;

#pragma unroll 16
        for (int k = 0; k < 64; k++) {
            float4 bA = Os4[k * 64 + tx * 2];
            float4 bB = Os4[k * 64 + tx * 2 + 1];
#pragma unroll
            for (int q = 0; q < 4; q++) {
                float a = Zs[(ty * 4 + q) * 64 + k];
                acc[q][0] += a * bA.x; acc[q][1] += a * bA.y;
                acc[q][2] += a * bA.z; acc[q][3] += a * bA.w;
                acc[q][4] += a * bB.x; acc[q][5] += a * bB.y;
                acc[q][6] += a * bB.z; acc[q][7] += a * bB.w;
            }
        }

#pragma unroll
        for (int q = 0; q < 4; q++) {
            float4 e0, e1;
            e0.x = __expf(acc[q][0]); e0.y = __expf(acc[q][1]);
            e0.z = __expf(acc[q][2]); e0.w = __expf(acc[q][3]);
            e1.x = __expf(acc[q][4]); e1.y = __expf(acc[q][5]);
            e1.z = __expf(acc[q][6]); e1.w = __expf(acc[q][7]);
            rsum[q] += (e0.x + e0.y) + (e0.z + e0.w) + (e1.x + e1.y) + (e1.z + e1.w);
            int row = b0 + ty * 4 + q;
            float4* op = (float4*)(out_norm + row * NRULES + ch * 256 + tx * 8);
            op[0] = e0; op[1] = e1;
        }
    }

#pragma unroll
    for (int off = 16; off > 0; off >>= 1)
#pragma unroll
        for (int q = 0; q < 4; q++)
            rsum[q] += __shfl_xor_sync(0xffffffffu, rsum[q], off);
    if (tx == 0)
#pragma unroll
        for (int q = 0; q < 4; q++) rs[ty * 4 + q] = rsum[q];
    __syncthreads();
    if (t < 32) g_inv[b0 + t] = 1.0f / (rs[t] + 1e-9f);
}

// =====================================================================
// k_norm: scale firing -> norm_fs (fp32 output) AND emit bf16 hi/lo A.
// =====================================================================
__global__ void k_norm(float* __restrict__ out_norm)
{
    int i = blockIdx.x * 256 + threadIdx.x;   // float4 index, 1,048,576 total
    float4* p = (float4*)out_norm;
    float4 v = p[i];
    float inv = g_inv[i >> 8];
    v.x *= inv; v.y *= inv; v.z *= inv; v.w *= inv;
    p[i] = v;

    __nv_bfloat16 hx = __float2bfloat16_rn(v.x), hy = __float2bfloat16_rn(v.y);
    __nv_bfloat16 hz = __float2bfloat16_rn(v.z), hw = __float2bfloat16_rn(v.w);
    __nv_bfloat162* Ah2 = (__nv_bfloat162*)g_Ah;
    __nv_bfloat162* Al2 = (__nv_bfloat162*)g_Al;
    Ah2[i * 2 + 0] = __nv_bfloat162(hx, hy);
    Ah2[i * 2 + 1] = __nv_bfloat162(hz, hw);
    Al2[i * 2 + 0] = __nv_bfloat162(__float2bfloat16_rn(v.x - __bfloat162float(hx)),
                                    __float2bfloat16_rn(v.y - __bfloat162float(hy)));
    Al2[i * 2 + 1] = __nv_bfloat162(__float2bfloat16_rn(v.z - __bfloat162float(hz)),
                                    __float2bfloat16_rn(v.w - __bfloat162float(hw)));
}

// =====================================================================
// k_tgemm: mma.sync (HMMA) bf16 GEMM with hi/lo compensation.
// CTA: 128x192 output, 256 thr = 8 warps (4M x 2N), warp tile 32x96.
// Register accumulation across all 12 K-chunks; cp.async double buffer.
// grid (32 M-tiles, KSPLIT).
// =====================================================================
#define STAGE_BYTES 40960   // A 16KB + B 24KB
#define SMB_OFF     16384
#define SM_TOT_G    (2 * STAGE_BYTES)

__device__ __forceinline__ void load_chunk(uint32_t sbase, int stage, int mt, int kg, int t)
{
    int pass = kg >> 10, ko = kg & 1023;
    const __nv_bfloat16* Asrc = (pass == 2 ? g_Al : g_Ah) + (size_t)(mt * 128) * NRULES + ko;
    const __nv_bfloat16* Bsrc = (pass == 1 ? g_Bl : g_Bh) + ko;
    uint32_t sA = sbase + stage * STAGE_BYTES;
    uint32_t sB = sA + SMB_OFF;
#pragma unroll
    for (int i = 0; i < 4; i++) {          // A: 1024 x 16B
        int f = t + i * 256, row = f >> 3, c = f & 7;
        CP_ASYNC16(sA + SWZ128(row * 128 + c * 16), Asrc + row * NRULES + c * 8);
    }
#pragma unroll
    for (int i = 0; i < 6; i++) {          // B: 1536 x 16B
        int f = t + i * 256, row = f >> 3, c = f & 7;
        CP_ASYNC16(sB + SWZ128(row * 128 + c * 16), Bsrc + row * NRULES + c * 8);
    }
}

__global__ __launch_bounds__(256, 1) void k_tgemm()
{
    uint32_t sbase = smem_u32(dyn_smem);
    const int t = threadIdx.x;
    const int lane = t & 31;
    const int wid = t >> 5;
    const int warp_m = wid >> 1;          // 0..3 -> rows warp_m*32
    const int warp_n = wid & 1;           // 0..1 -> cols warp_n*96
    const int mt = blockIdx.x;
    const int ks = blockIdx.y;

    float acc[2][12][4];
#pragma unroll
    for (int mi = 0; mi < 2; mi++)
#pragma unroll
        for (int ni = 0; ni < 12; ni++)
#pragma unroll
            for (int q = 0; q < 4; q++) acc[mi][ni][q] = 0.f;

    load_chunk(sbase, 0, mt, ks * KLOC, t);
    CP_COMMIT();

    for (int ch = 0; ch < NCH; ch++) {
        if (ch + 1 < NCH) {
            load_chunk(sbase, (ch + 1) & 1, mt, ks * KLOC + (ch + 1) * 64, t);
            CP_COMMIT();
            CP_WAIT1();
        } else {
            CP_WAIT0();
        }
        __syncthreads();

        uint32_t sA = sbase + (ch & 1) * STAGE_BYTES;
        uint32_t sB = sA + SMB_OFF;

#pragma unroll
        for (int kk = 0; kk < 4; kk++) {   // k16 steps within K=64 chunk
            uint32_t a[2][4];
#pragma unroll
            for (int mi = 0; mi < 2; mi++) {
                int r = warp_m * 32 + mi * 16 + (lane & 15);
                uint32_t off = (uint32_t)(r * 128 + kk * 32 + (lane >> 4) * 16);
                LDSM_X4(a[mi][0], a[mi][1], a[mi][2], a[mi][3], sA + SWZ128(off));
            }
            uint32_t b[12][2];
#pragma unroll
            for (int pr = 0; pr < 6; pr++) {
                int nt = 2 * pr + (lane >> 4);
                int r = warp_n * 96 + nt * 8 + (lane & 7);
                uint32_t off = (uint32_t)(r * 128 + kk * 32 + ((lane >> 3) & 1) * 16);
                LDSM_X4(b[2 * pr][0], b[2 * pr][1], b[2 * pr + 1][0], b[2 * pr + 1][1],
                        sB + SWZ128(off));
            }
#pragma unroll
            for (int mi = 0; mi < 2; mi++)
#pragma unroll
                for (int ni = 0; ni < 12; ni++)
                    mma16816(acc[mi][ni], a[mi], b[ni]);
        }
        __syncthreads();
    }

    // epilogue: write fp32 partials
    float* Tp = g_Tp + (size_t)ks * (BATCH * NPAD);
    int r0 = mt * 128 + warp_m * 32 + (lane >> 2);
    int c0 = warp_n * 96 + (lane & 3) * 2;
#pragma unroll
    for (int mi = 0; mi < 2; mi++)
#pragma unroll
        for (int ni = 0; ni < 12; ni++) {
            int row = r0 + mi * 16, col = c0 + ni * 8;
            *(float2*)(Tp + (size_t)row * NPAD + col) =
                make_float2(acc[mi][ni][0], acc[mi][ni][1]);
            *(float2*)(Tp + (size_t)(row + 8) * NPAD + col) =
                make_float2(acc[mi][ni][2], acc[mi][ni][3]);
        }
}

// =====================================================================
// k_yhat: y[b,c] = sum_i xext[b,i] * sum_s Tp[s][b, i*10+c]
// =====================================================================
__global__ void k_yhat(const float* __restrict__ xext, float* __restrict__ out_y)
{
    int i = blockIdx.x * 256 + threadIdx.x;
    if (i >= BATCH * NCLS) return;
    int b = i / NCLS, c = i % NCLS;
    const float* tb = g_Tp + (size_t)b * NPAD;
    const float* xe = xext + b * IEXT;
    float y = 0.f;
#pragma unroll
    for (int ii = 0; ii < IEXT; ii++) {
        float tsum = 0.f;
#pragma unroll
        for (int s = 0; s < KSPLIT; s++)
            tsum += tb[(size_t)s * (BATCH * NPAD) + ii * NCLS + c];
        y += xe[ii] * tsum;
    }
    out_y[i] = y;
}

// =====================================================================
extern "C" void kernel_launch(void* const* d_in, const int* in_sizes, int n_in,
                              void* d_out, int out_size)
{
    const float* x       = (const float*)d_in[0];
    const float* centers = (const float*)d_in[1];
    const float* widths  = (const float*)d_in[2];
    const float* conseq  = (const float*)d_in[3];
    const int*   ridx    = (const int*)  d_in[4];

    float* out      = (float*)d_out;
    float* out_y    = out;
    float* out_norm = out + BATCH * NCLS;
    float* out_xext = out + BATCH * NCLS + BATCH * NRULES;

    const int SMEM_FIRE = (32 * 64 + 64 * 256 + 32) * (int)sizeof(float);
    cudaFuncSetAttribute(k_fire,  cudaFuncAttributeMaxDynamicSharedMemorySize, SMEM_FIRE);
    cudaFuncSetAttribute(k_tgemm, cudaFuncAttributeMaxDynamicSharedMemorySize, SM_TOT_G);

    k_prep<<<2320, 256>>>(x, centers, widths, conseq, ridx, out_xext);
    k_fire<<<128, 256, SMEM_FIRE>>>(out_norm);
    k_norm<<<4096, 256>>>(out_norm);
    dim3 gg(32, KSPLIT);
    k_tgemm<<<gg, 256, SM_TOT_G>>>();
    k_yhat<<<160, 256>>>(out_xext, out_y);
}

// round 5
// speedup vs baseline: 2.4502x; 1.4298x over previous
#include <cuda_runtime.h>
#include <cuda_bf16.h>
#include <cstdint>

#define BATCH   4096
#define DIM     16
#define NRULES  1024
#define NCLS    10
#define IEXT    17
#define NCOLS   170
#define NPAD    192
#define KSPLIT  4
#define KTOT    3072                 // 3 passes x 1024 (ah*bh, ah*bl, al*bh)
#define KLOC    (KTOT / KSPLIT)      // 768
#define NCH     (KLOC / 64)          // 12

// single TU-wide dynamic smem symbol
extern __shared__ char dyn_smem[];

// ---------------- static device scratch ----------------
__device__ __nv_bfloat16 g_Zb[BATCH * 192];      // [b][zh(64)|zl(64)|zl2(64)]
__device__ __nv_bfloat16 g_OTb[NRULES * 192];    // one-hot bf16, [r][j] x3 copies
__device__ __nv_bfloat16 g_Ah[BATCH * NRULES];
__device__ __nv_bfloat16 g_Al[BATCH * NRULES];
__device__ __nv_bfloat16 g_Bh[NPAD * NRULES];
__device__ __nv_bfloat16 g_Bl[NPAD * NRULES];
__device__ float         g_Tp[KSPLIT * BATCH * NPAD];   // 12.6 MB partials

// ---------------- helpers ----------------
__device__ __forceinline__ uint32_t smem_u32(const void* p) {
    uint32_t a;
    asm("{ .reg .u64 t; cvta.to.shared.u64 t, %1; cvt.u32.u64 %0, t; }" : "=r"(a) : "l"(p));
    return a;
}
#define SWZ128(o) ((o) ^ (((o) >> 3) & 0x70))

#define CP_ASYNC16(dst, src) \
    asm volatile("cp.async.cg.shared.global [%0], [%1], 16;" :: "r"(dst), "l"(src))
#define CP_COMMIT() asm volatile("cp.async.commit_group;" ::: "memory")
#define CP_WAIT1()  asm volatile("cp.async.wait_group 1;" ::: "memory")
#define CP_WAIT0()  asm volatile("cp.async.wait_group 0;" ::: "memory")

#define LDSM_X4(r0, r1, r2, r3, addr)                                        \
    asm volatile("ldmatrix.sync.aligned.m8n8.x4.shared.b16 {%0,%1,%2,%3}, [%4];" \
        : "=r"(r0), "=r"(r1), "=r"(r2), "=r"(r3) : "r"(addr))

__device__ __forceinline__ void mma16816(float* c, const uint32_t* a, const uint32_t* b) {
    asm volatile(
        "mma.sync.aligned.m16n8k16.row.col.f32.bf16.bf16.f32 "
        "{%0,%1,%2,%3}, {%4,%5,%6,%7}, {%8,%9}, {%0,%1,%2,%3};"
        : "+f"(c[0]), "+f"(c[1]), "+f"(c[2]), "+f"(c[3])
        : "r"(a[0]), "r"(a[1]), "r"(a[2]), "r"(a[3]), "r"(b[0]), "r"(b[1]));
}

// =====================================================================
// k_prep: OTb (one-hot bf16, 3 copies), Bh/Bl, Zb (3-way bf16 split),
//         x_ext.  196608 + 196608 + 262144 + 69632 = 724992 = 2832*256
// =====================================================================
__global__ void k_prep(const float* __restrict__ x,
                       const float* __restrict__ centers,
                       const float* __restrict__ widths,
                       const float* __restrict__ conseq,
                       const int*   __restrict__ ridx,
                       float* __restrict__ out_xext)
{
    int i = blockIdx.x * 256 + threadIdx.x;
    if (i < 196608) {
        int r = i / 192, q = i % 192;
        int j = q & 63;
        int d = j >> 2, m = j & 3;
        g_OTb[i] = __float2bfloat16((ridx[d * NRULES + r] == m) ? 1.0f : 0.0f);
    } else if (i < 2 * 196608) {
        int e = i - 196608;
        int n = e >> 10, k = e & 1023;
        float v = (n < NCOLS) ? conseq[k * NCOLS + n] : 0.0f;
        __nv_bfloat16 h = __float2bfloat16_rn(v);
        g_Bh[e] = h;
        g_Bl[e] = __float2bfloat16_rn(v - __bfloat162float(h));
    } else if (i < 2 * 196608 + 262144) {
        int e = i - 2 * 196608;
        int b = e >> 6, j = e & 63;
        int d = j >> 2;
        float xv = x[b * DIM + d];
        float c  = centers[j];
        float w  = widths[j];
        float df = xv - c;
        float z  = -(df * df) / (2.0f * w * w) + 1e-9f;
        __nv_bfloat16 h = __float2bfloat16_rn(z);
        float r1 = z - __bfloat162float(h);
        __nv_bfloat16 l = __float2bfloat16_rn(r1);
        float r2 = r1 - __bfloat162float(l);
        g_Zb[b * 192 + j]       = h;
        g_Zb[b * 192 + 64 + j]  = l;
        g_Zb[b * 192 + 128 + j] = __float2bfloat16_rn(r2);
    } else {
        int e = i - (2 * 196608 + 262144);
        if (e < BATCH * IEXT) {
            int b = e / IEXT, ii = e % IEXT;
            out_xext[e] = (ii < DIM) ? x[b * DIM + ii] : 1.0f;
        }
    }
}

// =====================================================================
// k_fire: HMMA GEMM  logits = Zb[4096x192] @ OTb^T[192x1024], exp fused.
// CTA 128 rows x 128 rules, 256 thr (4M x 2N warps, warp 32x64).
// grid (32 M, 8 rule-chunks). 2 CTAs/SM. Writes UNNORMALIZED exp.
// =====================================================================
#define F_STAGE 32768   // A 16KB + B 16KB
#define F_SMB   16384

__device__ __forceinline__ void load_fchunk(uint32_t sbase, int stage,
                                            int mt, int rt0, int ck, int t)
{
    const __nv_bfloat16* Asrc = g_Zb  + (size_t)(mt * 128) * 192 + ck * 64;
    const __nv_bfloat16* Bsrc = g_OTb + (size_t)rt0 * 192 + ck * 64;
    uint32_t sA = sbase + stage * F_STAGE;
    uint32_t sB = sA + F_SMB;
#pragma unroll
    for (int i = 0; i < 4; i++) {          // A: 128 rows x 128B
        int f = t + i * 256, row = f >> 3, c = f & 7;
        CP_ASYNC16(sA + SWZ128(row * 128 + c * 16), Asrc + row * 192 + c * 8);
    }
#pragma unroll
    for (int i = 0; i < 4; i++) {          // B: 128 rows x 128B
        int f = t + i * 256, row = f >> 3, c = f & 7;
        CP_ASYNC16(sB + SWZ128(row * 128 + c * 16), Bsrc + row * 192 + c * 8);
    }
}

__global__ __launch_bounds__(256, 2) void k_fire(float* __restrict__ out_norm)
{
    uint32_t sbase = smem_u32(dyn_smem);
    const int t = threadIdx.x;
    const int lane = t & 31;
    const int wid = t >> 5;
    const int warp_m = wid >> 1;
    const int warp_n = wid & 1;
    const int mt  = blockIdx.x;
    const int rt0 = blockIdx.y * 128;

    float acc[2][8][4];
#pragma unroll
    for (int mi = 0; mi < 2; mi++)
#pragma unroll
        for (int ni = 0; ni < 8; ni++)
#pragma unroll
            for (int q = 0; q < 4; q++) acc[mi][ni][q] = 0.f;

    load_fchunk(sbase, 0, mt, rt0, 0, t);
    CP_COMMIT();

    for (int ch = 0; ch < 3; ch++) {
        if (ch + 1 < 3) {
            load_fchunk(sbase, (ch + 1) & 1, mt, rt0, ch + 1, t);
            CP_COMMIT();
            CP_WAIT1();
        } else {
            CP_WAIT0();
        }
        __syncthreads();

        uint32_t sA = sbase + (ch & 1) * F_STAGE;
        uint32_t sB = sA + F_SMB;

#pragma unroll
        for (int kk = 0; kk < 4; kk++) {
            uint32_t a[2][4];
#pragma unroll
            for (int mi = 0; mi < 2; mi++) {
                int r = warp_m * 32 + mi * 16 + (lane & 15);
                uint32_t off = (uint32_t)(r * 128 + kk * 32 + (lane >> 4) * 16);
                LDSM_X4(a[mi][0], a[mi][1], a[mi][2], a[mi][3], sA + SWZ128(off));
            }
            uint32_t b[8][2];
#pragma unroll
            for (int pr = 0; pr < 4; pr++) {
                int nt = 2 * pr + (lane >> 4);
                int r = warp_n * 64 + nt * 8 + (lane & 7);
                uint32_t off = (uint32_t)(r * 128 + kk * 32 + ((lane >> 3) & 1) * 16);
                LDSM_X4(b[2 * pr][0], b[2 * pr][1], b[2 * pr + 1][0], b[2 * pr + 1][1],
                        sB + SWZ128(off));
            }
#pragma unroll
            for (int mi = 0; mi < 2; mi++)
#pragma unroll
                for (int ni = 0; ni < 8; ni++)
                    mma16816(acc[mi][ni], a[mi], b[ni]);
        }
        __syncthreads();
    }

    // epilogue: exp + store unnormalized firing
    int r0 = mt * 128 + warp_m * 32 + (lane >> 2);
    int c0 = rt0 + warp_n * 64 + (lane & 3) * 2;
#pragma unroll
    for (int mi = 0; mi < 2; mi++)
#pragma unroll
        for (int ni = 0; ni < 8; ni++) {
            int row = r0 + mi * 16, col = c0 + ni * 8;
            *(float2*)(out_norm + (size_t)row * NRULES + col) =
                make_float2(__expf(acc[mi][ni][0]), __expf(acc[mi][ni][1]));
            *(float2*)(out_norm + (size_t)(row + 8) * NRULES + col) =
                make_float2(__expf(acc[mi][ni][2]), __expf(acc[mi][ni][3]));
        }
}

// =====================================================================
// k_norm: warp per batch row: rowsum -> normalize in place -> bf16 hi/lo.
// 512 blocks x 256 thr (8 rows/block).
// =====================================================================
__global__ void k_norm(float* __restrict__ out_norm)
{
    const int lane = threadIdx.x & 31;
    const int w = threadIdx.x >> 5;
    const int b = blockIdx.x * 8 + w;

    float4* p = (float4*)(out_norm + (size_t)b * NRULES);
    float4 v[8];
    float s = 0.f;
#pragma unroll
    for (int i = 0; i < 8; i++) {
        v[i] = p[lane + i * 32];
        s += (v[i].x + v[i].y) + (v[i].z + v[i].w);
    }
#pragma unroll
    for (int off = 16; off > 0; off >>= 1)
        s += __shfl_xor_sync(0xffffffffu, s, off);
    float inv = 1.0f / (s + 1e-9f);

    __nv_bfloat162* Ah2 = (__nv_bfloat162*)(g_Ah + (size_t)b * NRULES);
    __nv_bfloat162* Al2 = (__nv_bfloat162*)(g_Al + (size_t)b * NRULES);
#pragma unroll
    for (int i = 0; i < 8; i++) {
        float4 u = v[i];
        u.x *= inv; u.y *= inv; u.z *= inv; u.w *= inv;
        p[lane + i * 32] = u;
        __nv_bfloat16 hx = __float2bfloat16_rn(u.x), hy = __float2bfloat16_rn(u.y);
        __nv_bfloat16 hz = __float2bfloat16_rn(u.z), hw = __float2bfloat16_rn(u.w);
        int q = (lane + i * 32) * 2;
        Ah2[q]     = __nv_bfloat162(hx, hy);
        Ah2[q + 1] = __nv_bfloat162(hz, hw);
        Al2[q]     = __nv_bfloat162(__float2bfloat16_rn(u.x - __bfloat162float(hx)),
                                    __float2bfloat16_rn(u.y - __bfloat162float(hy)));
        Al2[q + 1] = __nv_bfloat162(__float2bfloat16_rn(u.z - __bfloat162float(hz)),
                                    __float2bfloat16_rn(u.w - __bfloat162float(hw)));
    }
}

// =====================================================================
// k_tgemm: HMMA bf16 GEMM, hi/lo compensated (3 passes, K_eff=3072).
// CTA 128x96, 256 thr (4M x 2N warps, warp 32x48), 2 CTAs/SM.
// grid (32 M, 2 Ntile x 4 Ksplit).
// =====================================================================
#define STAGE_BYTES 28672   // A 16KB + B 12KB
#define SMB_OFF     16384
#define SM_TOT_G    (2 * STAGE_BYTES)

__device__ __forceinline__ void load_chunk(uint32_t sbase, int stage, int mt, int nt,
                                           int kg, int t)
{
    int pass = kg >> 10, ko = kg & 1023;
    const __nv_bfloat16* Asrc = (pass == 2 ? g_Al : g_Ah) + (size_t)(mt * 128) * NRULES + ko;
    const __nv_bfloat16* Bsrc = (pass == 1 ? g_Bl : g_Bh) + (size_t)(nt * 96) * NRULES + ko;
    uint32_t sA = sbase + stage * STAGE_BYTES;
    uint32_t sB = sA + SMB_OFF;
#pragma unroll
    for (int i = 0; i < 4; i++) {          // A: 128 rows x 128B
        int f = t + i * 256, row = f >> 3, c = f & 7;
        CP_ASYNC16(sA + SWZ128(row * 128 + c * 16), Asrc + row * NRULES + c * 8);
    }
#pragma unroll
    for (int i = 0; i < 3; i++) {          // B: 96 rows x 128B
        int f = t + i * 256, row = f >> 3, c = f & 7;
        CP_ASYNC16(sB + SWZ128(row * 128 + c * 16), Bsrc + row * NRULES + c * 8);
    }
}

__global__ __launch_bounds__(256, 2) void k_tgemm()
{
    uint32_t sbase = smem_u32(dyn_smem);
    const int t = threadIdx.x;
    const int lane = t & 31;
    const int wid = t >> 5;
    const int warp_m = wid >> 1;
    const int warp_n = wid & 1;
    const int mt = blockIdx.x;
    const int nt = blockIdx.y & 1;
    const int ks = blockIdx.y >> 1;

    float acc[2][6][4];
#pragma unroll
    for (int mi = 0; mi < 2; mi++)
#pragma unroll
        for (int ni = 0; ni < 6; ni++)
#pragma unroll
            for (int q = 0; q < 4; q++) acc[mi][ni][q] = 0.f;

    load_chunk(sbase, 0, mt, nt, ks * KLOC, t);
    CP_COMMIT();

    for (int ch = 0; ch < NCH; ch++) {
        if (ch + 1 < NCH) {
            load_chunk(sbase, (ch + 1) & 1, mt, nt, ks * KLOC + (ch + 1) * 64, t);
            CP_COMMIT();
            CP_WAIT1();
        } else {
            CP_WAIT0();
        }
        __syncthreads();

        uint32_t sA = sbase + (ch & 1) * STAGE_BYTES;
        uint32_t sB = sA + SMB_OFF;

#pragma unroll
        for (int kk = 0; kk < 4; kk++) {
            uint32_t a[2][4];
#pragma unroll
            for (int mi = 0; mi < 2; mi++) {
                int r = warp_m * 32 + mi * 16 + (lane & 15);
                uint32_t off = (uint32_t)(r * 128 + kk * 32 + (lane >> 4) * 16);
                LDSM_X4(a[mi][0], a[mi][1], a[mi][2], a[mi][3], sA + SWZ128(off));
            }
            uint32_t b[6][2];
#pragma unroll
            for (int pr = 0; pr < 3; pr++) {
                int nt8 = 2 * pr + (lane >> 4);
                int r = warp_n * 48 + nt8 * 8 + (lane & 7);
                uint32_t off = (uint32_t)(r * 128 + kk * 32 + ((lane >> 3) & 1) * 16);
                LDSM_X4(b[2 * pr][0], b[2 * pr][1], b[2 * pr + 1][0], b[2 * pr + 1][1],
                        sB + SWZ128(off));
            }
#pragma unroll
            for (int mi = 0; mi < 2; mi++)
#pragma unroll
                for (int ni = 0; ni < 6; ni++)
                    mma16816(acc[mi][ni], a[mi], b[ni]);
        }
        __syncthreads();
    }

    // epilogue: write fp32 partials
    float* Tp = g_Tp + (size_t)ks * (BATCH * NPAD);
    int r0 = mt * 128 + warp_m * 32 + (lane >> 2);
    int c0 = nt * 96 + warp_n * 48 + (lane & 3) * 2;
#pragma unroll
    for (int mi = 0; mi < 2; mi++)
#pragma unroll
        for (int ni = 0; ni < 6; ni++) {
            int row = r0 + mi * 16, col = c0 + ni * 8;
            *(float2*)(Tp + (size_t)row * NPAD + col) =
                make_float2(acc[mi][ni][0], acc[mi][ni][1]);
            *(float2*)(Tp + (size_t)(row + 8) * NPAD + col) =
                make_float2(acc[mi][ni][2], acc[mi][ni][3]);
        }
}

// =====================================================================
// k_yhat: y[b,c] = sum_i xext[b,i] * sum_s Tp[s][b, i*10+c]
// =====================================================================
__global__ void k_yhat(const float* __restrict__ xext, float* __restrict__ out_y)
{
    int i = blockIdx.x * 256 + threadIdx.x;
    if (i >= BATCH * NCLS) return;
    int b = i / NCLS, c = i % NCLS;
    const float* tb = g_Tp + (size_t)b * NPAD;
    const float* xe = xext + b * IEXT;
    float y = 0.f;
#pragma unroll
    for (int ii = 0; ii < IEXT; ii++) {
        float tsum = 0.f;
#pragma unroll
        for (int s = 0; s < KSPLIT; s++)
            tsum += tb[(size_t)s * (BATCH * NPAD) + ii * NCLS + c];
        y += xe[ii] * tsum;
    }
    out_y[i] = y;
}

// =====================================================================
extern "C" void kernel_launch(void* const* d_in, const int* in_sizes, int n_in,
                              void* d_out, int out_size)
{
    const float* x       = (const float*)d_in[0];
    const float* centers = (const float*)d_in[1];
    const float* widths  = (const float*)d_in[2];
    const float* conseq  = (const float*)d_in[3];
    const int*   ridx    = (const int*)  d_in[4];

    float* out      = (float*)d_out;
    float* out_y    = out;
    float* out_norm = out + BATCH * NCLS;
    float* out_xext = out + BATCH * NCLS + BATCH * NRULES;

    cudaFuncSetAttribute(k_fire,  cudaFuncAttributeMaxDynamicSharedMemorySize, 2 * F_STAGE);
    cudaFuncSetAttribute(k_tgemm, cudaFuncAttributeMaxDynamicSharedMemorySize, SM_TOT_G);

    k_prep<<<2832, 256>>>(x, centers, widths, conseq, ridx, out_xext);
    k_fire<<<dim3(32, 8), 256, 2 * F_STAGE>>>(out_norm);
    k_norm<<<512, 256>>>(out_norm);
    k_tgemm<<<dim3(32, 8), 256, SM_TOT_G>>>();
    k_yhat<<<160, 256>>>(out_xext, out_y);
}